// round 15
// baseline (speedup 1.0000x reference)
#include <cuda_runtime.h>
#include <math.h>

#define PATCH    32
#define HP       256
#define WP       256
#define NPATCH   (HP * WP)        // 65536
#define IMG_W    8192
#define IMG_W4   (IMG_W / 4)      // 2048 float4 per row
#define PPB      64               // patches per CTA (8 warps x 8 iters)
#define NGRID1   (NPATCH / PPB)   // 1024 CTAs

// ln(0.04 * sqrt(2*pi)) = -2.2999372...
#define LOG_NORM_CONST (-2.2999372199f)

// Per-CTA partials: (pos_sum, neg_sum, pos_count, unused)
__device__ float4 g_part[NGRID1];
__device__ unsigned int g_count;   // zero-initialized; reset by last CTA

// Release-ordered arrival: orders this CTA's prior global stores before the
// counter bump WITHOUT a gpu-scope membar (no CCTL.IVALL / L1D flush).
__device__ __forceinline__ unsigned int arrive_release(unsigned int* p) {
    unsigned int old;
    asm volatile("atom.release.gpu.global.add.u32 %0, [%1], 1;"
                 : "=r"(old) : "l"(p) : "memory");
    return old;
}

// Fused kernel: warp-per-patch streaming reduce + last-CTA finish.
// R5 configuration (best measured 43.5us / 79.3% DRAM), with the per-CTA
// __threadfence replaced by a release atomic arrival (fence only in the
// single last CTA).
__global__ void __launch_bounds__(256, 8)
fused_kernel(const float* __restrict__ x, const float* __restrict__ tmask,
             float* __restrict__ out) {
    const int tid = threadIdx.x;
    const int w   = tid >> 5;            // warp 0..7
    const int l   = tid & 31;            // lane
    const int p_base = blockIdx.x * PPB; // first patch of this CTA

    __shared__ float means[PPB];

    const int lrow = l >> 3;             // 0..3 base row
    const int lq   = l & 7;              // float4 within 128B row segment

    #pragma unroll
    for (int t = 0; t < 8; t++) {
        const int p  = p_base + t * 8 + w;
        const int ph = p >> 8;
        const int pw = p & 255;
        const float4* p4 = (const float4*)x
                         + (size_t)(ph * PATCH) * IMG_W4 + (size_t)pw * 8;

        float s = 0.0f;
        #pragma unroll
        for (int k = 0; k < 8; k++) {    // 8 independent loads in flight
            const float4 v = __ldcs(&p4[(size_t)(lrow + 4 * k) * IMG_W4 + lq]);
            s += (v.x + v.y) + (v.z + v.w);
        }

        #pragma unroll
        for (int o = 16; o > 0; o >>= 1)
            s += __shfl_xor_sync(0xffffffffu, s, o);

        if (l == 0) means[t * 8 + w] = s * (1.0f / (PATCH * PATCH));
    }
    __syncthreads();

    // Tail: 64 parallel term computations, then block reduce.
    float ps = 0.0f, ns = 0.0f, pc = 0.0f;
    if (tid < PPB) {
        const float mean = means[tid];
        const float z = (mean - 0.34f) * 25.0f;
        const float logpdf = -0.5f * z * z - LOG_NORM_CONST;
        const float pos_t = -logf(expf(logpdf) + 1e-6f);
        const float neg_t = mean * mean;
        const float mk = (tmask[p_base + tid] >= 0.5f) ? 1.0f : 0.0f;
        ps = pos_t * mk;
        ns = neg_t * (1.0f - mk);
        pc = mk;
    }

    if (tid < 64) {
        #pragma unroll
        for (int o = 16; o > 0; o >>= 1) {
            ps += __shfl_xor_sync(0xffffffffu, ps, o);
            ns += __shfl_xor_sync(0xffffffffu, ns, o);
            pc += __shfl_xor_sync(0xffffffffu, pc, o);
        }
    }
    __shared__ float3 pr[2];
    if (tid == 0 || tid == 32) pr[tid >> 5] = make_float3(ps, ns, pc);
    __syncthreads();

    __shared__ bool s_last;
    if (tid == 0) {
        const float3 a = pr[0], b = pr[1];
        g_part[blockIdx.x] = make_float4(a.x + b.x, a.y + b.y, a.z + b.z, 0.0f);
        const unsigned int old = arrive_release(&g_count);   // no L1 flush
        s_last = (old == NGRID1 - 1);
    }
    __syncthreads();

    if (!s_last) return;

    // ---- Last CTA: acquire once, reduce 1024 partials in fixed order ----
    __threadfence();   // acquire; executes in exactly one CTA

    float fps = 0.0f, fns = 0.0f, fpc = 0.0f;
    #pragma unroll
    for (int k = 0; k < NGRID1 / 256; k++) {      // 4 independent loads
        const float4 p = g_part[tid + k * 256];
        fps += p.x; fns += p.y; fpc += p.z;
    }

    #pragma unroll
    for (int o = 16; o > 0; o >>= 1) {
        fps += __shfl_xor_sync(0xffffffffu, fps, o);
        fns += __shfl_xor_sync(0xffffffffu, fns, o);
        fpc += __shfl_xor_sync(0xffffffffu, fpc, o);
    }

    __shared__ float f_ps[8], f_ns[8], f_pc[8];
    if (l == 0) { f_ps[w] = fps; f_ns[w] = fns; f_pc[w] = fpc; }
    __syncthreads();

    if (tid < 8) {
        fps = f_ps[tid]; fns = f_ns[tid]; fpc = f_pc[tid];
        #pragma unroll
        for (int o = 4; o > 0; o >>= 1) {
            fps += __shfl_xor_sync(0xffu, fps, o);
            fns += __shfl_xor_sync(0xffu, fns, o);
            fpc += __shfl_xor_sync(0xffu, fpc, o);
        }
        if (tid == 0) {
            const float fnc = (float)NPATCH - fpc;
            out[0] = fps / fpc + fns / fnc;
            g_count = 0;                  // reset for next graph replay
        }
    }
}

extern "C" void kernel_launch(void* const* d_in, const int* in_sizes, int n_in,
                              void* d_out, int out_size) {
    const float* unet  = (const float*)d_in[0];   // [1,1,8192,8192] fp32
    const float* tmask = (const float*)d_in[1];   // [1,256,256] fp32
    float* out = (float*)d_out;

    fused_kernel<<<NGRID1, 256>>>(unet, tmask, out);
}

// round 16
// speedup vs baseline: 1.0368x; 1.0368x over previous
#include <cuda_runtime.h>
#include <math.h>

#define PATCH    32
#define HP       256
#define WP       256
#define NPATCH   (HP * WP)        // 65536
#define IMG_W    8192
#define IMG_W4   (IMG_W / 4)      // 2048 float4 per row
#define PPB      64               // patches per CTA (8 warps x 8 iters)
#define NGRID1   (NPATCH / PPB)   // 1024 CTAs

// ln(0.04 * sqrt(2*pi)) = -2.2999372...
#define LOG_NORM_CONST (-2.2999372199f)

// Per-CTA partials: (pos_sum, neg_sum, pos_count, unused)
__device__ float4 g_part[NGRID1];
__device__ unsigned int g_count;   // zero-initialized; reset by last CTA

// FINAL kernel: warp-per-patch streaming reduce + last-CTA finish.
// Best measured: 43.5us / 79.3% DRAM / 6.28 TB/s (plateau 44.5 +/- 1us).
// Grid 1024 x 256 threads; each warp reduces one 32x32 patch per iteration
// (lanes cover 4 rows x 8 float4; 8 independent loads in flight), 8 patches
// per warp; per-patch shfl reduces hidden under memory latency; 64 pos/neg
// terms + mask fused in the CTA tail; single fenced last-CTA finish in
// fixed tree order (bit-deterministic, graph-replayable).
__global__ void __launch_bounds__(256, 8)
fused_kernel(const float* __restrict__ x, const float* __restrict__ tmask,
             float* __restrict__ out) {
    const int tid = threadIdx.x;
    const int w   = tid >> 5;            // warp 0..7
    const int l   = tid & 31;            // lane
    const int p_base = blockIdx.x * PPB; // first patch of this CTA

    __shared__ float means[PPB];

    const int lrow = l >> 3;             // 0..3 base row
    const int lq   = l & 7;              // float4 within 128B row segment

    #pragma unroll
    for (int t = 0; t < 8; t++) {
        const int p  = p_base + t * 8 + w;
        const int ph = p >> 8;
        const int pw = p & 255;
        const float4* p4 = (const float4*)x
                         + (size_t)(ph * PATCH) * IMG_W4 + (size_t)pw * 8;

        float s = 0.0f;
        #pragma unroll
        for (int k = 0; k < 8; k++) {    // 8 independent loads in flight
            const float4 v = __ldcs(&p4[(size_t)(lrow + 4 * k) * IMG_W4 + lq]);
            s += (v.x + v.y) + (v.z + v.w);
        }

        #pragma unroll
        for (int o = 16; o > 0; o >>= 1)
            s += __shfl_xor_sync(0xffffffffu, s, o);

        if (l == 0) means[t * 8 + w] = s * (1.0f / (PATCH * PATCH));
    }
    __syncthreads();

    // Tail: 64 parallel term computations, then block reduce.
    float ps = 0.0f, ns = 0.0f, pc = 0.0f;
    if (tid < PPB) {
        const float mean = means[tid];
        const float z = (mean - 0.34f) * 25.0f;
        const float logpdf = -0.5f * z * z - LOG_NORM_CONST;
        const float pos_t = -logf(expf(logpdf) + 1e-6f);
        const float neg_t = mean * mean;
        const float mk = (tmask[p_base + tid] >= 0.5f) ? 1.0f : 0.0f;
        ps = pos_t * mk;
        ns = neg_t * (1.0f - mk);
        pc = mk;
    }

    if (tid < 64) {
        #pragma unroll
        for (int o = 16; o > 0; o >>= 1) {
            ps += __shfl_xor_sync(0xffffffffu, ps, o);
            ns += __shfl_xor_sync(0xffffffffu, ns, o);
            pc += __shfl_xor_sync(0xffffffffu, pc, o);
        }
    }
    __shared__ float3 pr[2];
    if (tid == 0 || tid == 32) pr[tid >> 5] = make_float3(ps, ns, pc);
    __syncthreads();

    __shared__ bool s_last;
    if (tid == 0) {
        const float3 a = pr[0], b = pr[1];
        g_part[blockIdx.x] = make_float4(a.x + b.x, a.y + b.y, a.z + b.z, 0.0f);
        __threadfence();
        const unsigned int old = atomicAdd(&g_count, 1u);
        s_last = (old == NGRID1 - 1);
    }
    __syncthreads();

    if (!s_last) return;

    // ---- Last CTA: reduce all 1024 partials in fixed order (deterministic) ----
    float fps = 0.0f, fns = 0.0f, fpc = 0.0f;
    #pragma unroll
    for (int k = 0; k < NGRID1 / 256; k++) {      // 4 independent loads
        const float4 p = g_part[tid + k * 256];
        fps += p.x; fns += p.y; fpc += p.z;
    }

    #pragma unroll
    for (int o = 16; o > 0; o >>= 1) {
        fps += __shfl_xor_sync(0xffffffffu, fps, o);
        fns += __shfl_xor_sync(0xffffffffu, fns, o);
        fpc += __shfl_xor_sync(0xffffffffu, fpc, o);
    }

    __shared__ float f_ps[8], f_ns[8], f_pc[8];
    if (l == 0) { f_ps[w] = fps; f_ns[w] = fns; f_pc[w] = fpc; }
    __syncthreads();

    if (tid < 8) {
        fps = f_ps[tid]; fns = f_ns[tid]; fpc = f_pc[tid];
        #pragma unroll
        for (int o = 4; o > 0; o >>= 1) {
            fps += __shfl_xor_sync(0xffu, fps, o);
            fns += __shfl_xor_sync(0xffu, fns, o);
            fpc += __shfl_xor_sync(0xffu, fpc, o);
        }
        if (tid == 0) {
            const float fnc = (float)NPATCH - fpc;
            out[0] = fps / fpc + fns / fnc;
            g_count = 0;                  // reset for next graph replay
        }
    }
}

extern "C" void kernel_launch(void* const* d_in, const int* in_sizes, int n_in,
                              void* d_out, int out_size) {
    const float* unet  = (const float*)d_in[0];   // [1,1,8192,8192] fp32
    const float* tmask = (const float*)d_in[1];   // [1,256,256] fp32
    float* out = (float*)d_out;

    fused_kernel<<<NGRID1, 256>>>(unet, tmask, out);
}